// round 7
// baseline (speedup 1.0000x reference)
#include <cuda_runtime.h>
#include <cuda_bf16.h>
#include <math.h>

#define N 8192
#define EPS 1e-5f
#define FACT 2.0f
#define PD_EPS 1e-6f
#define CUTOFF 25.0f

#define RW 4                       // rows per work unit (one warp per unit)
#define UNITS (N / RW)             // 2048
#define CTAS 296                   // 2 CTAs/SM on 148 SMs
#define TPB 256                    // 16 warps/SM -> 4 per SMSP

__device__ float4 g_p2[N];   // packed {x, y, z, -0.5*(x^2+y^2+z^2)}
__device__ float g_pd[N];    // per-row pairwise distance
__device__ int g_ctr;        // work counter (units)
__device__ int g_done;       // completed-unit counter

// h = dot(p1, p2_j) - 0.5*|p2_j|^2   (argmax h == argmin d2; d2 = s1 - 2h)
__device__ __forceinline__ float hdot(float x, float y, float z, float4 p) {
    return fmaf(x, p.x, fmaf(y, p.y, fmaf(z, p.z, p.w)));
}

__global__ void prep_kernel(const float* __restrict__ pc2) {
    int j = blockIdx.x * blockDim.x + threadIdx.x;
    if (j == 0) { g_ctr = 0; g_done = 0; }   // re-seed every launch (graph-replay safe)
    if (j < N) {
        float x = pc2[j], y = pc2[N + j], z = pc2[2 * N + j];
        g_p2[j] = make_float4(x, y, z, -0.5f * fmaf(x, x, fmaf(y, y, z * z)));
    }
}

__global__ __launch_bounds__(TPB)
void soft_knn_kernel(const float* __restrict__ pc1, float* __restrict__ out,
                     int out_size) {
    const int lane = threadIdx.x & 31;
    const float4* __restrict__ p2 = g_p2;

    for (;;) {
        int u;
        if (lane == 0) u = atomicAdd(&g_ctr, 1);   // fully dynamic: SM-balanced
        u = __shfl_sync(0xFFFFFFFFu, u, 0);
        if (u >= UNITS) break;

        const int row0 = u * RW;

        float xs[RW], ys[RW], zs[RW], s1[RW];
#pragma unroll
        for (int r = 0; r < RW; r++) {
            int i = row0 + r;
            xs[r] = pc1[i];
            ys[r] = pc1[N + i];
            zs[r] = pc1[2 * N + i];
            s1[r] = fmaf(xs[r], xs[r], fmaf(ys[r], ys[r], zs[r] * zs[r]));
        }

        // ---- Pass 1: per-row hmax (j unrolled x4, loads front-batched) ----
        float hm[RW];
#pragma unroll
        for (int r = 0; r < RW; r++) hm[r] = -3.4e38f;

        for (int j = lane; j < N; j += 128) {
            float4 pa = p2[j];
            float4 pb = p2[j + 32];
            float4 pc = p2[j + 64];
            float4 pd = p2[j + 96];
#pragma unroll
            for (int r = 0; r < RW; r++) {
                float a = fmaxf(hdot(xs[r], ys[r], zs[r], pa),
                                hdot(xs[r], ys[r], zs[r], pb));
                float b = fmaxf(hdot(xs[r], ys[r], zs[r], pc),
                                hdot(xs[r], ys[r], zs[r], pd));
                hm[r] = fmaxf(hm[r], fmaxf(a, b));
            }
        }
#pragma unroll
        for (int r = 0; r < RW; r++) {
#pragma unroll
            for (int ofs = 16; ofs > 0; ofs >>= 1)
                hm[r] = fmaxf(hm[r], __shfl_xor_sync(0xFFFFFFFFu, hm[r], ofs));
        }

        // Thresholds; clamp to hmax so the argmax point ALWAYS qualifies
        // (identical fmaf chain in pass 2 reproduces h == hmax bitwise).
        float m[RW], hth[RW];
#pragma unroll
        for (int r = 0; r < RW; r++) {
            float mind2 = fmaf(-2.0f, hm[r], s1[r]);
            float mm = FACT / fmaxf(mind2, EPS);
            m[r] = mm;
            float t = (mm > CUTOFF) ? 0.5f * (s1[r] - FACT / (mm - CUTOFF)) : -3.4e38f;
            hth[r] = fminf(t, hm[r]);
        }

        // ---- Pass 2: one gate per (4 j x 4 rows) block ----
        float sw[RW], ax[RW], ay[RW], az[RW];
#pragma unroll
        for (int r = 0; r < RW; r++) { sw[r] = 0.f; ax[r] = 0.f; ay[r] = 0.f; az[r] = 0.f; }

        for (int j = lane; j < N; j += 128) {
            float4 ps[4] = {p2[j], p2[j + 32], p2[j + 64], p2[j + 96]};
            float h[RW][4];
            float g = -3.4e38f;
#pragma unroll
            for (int r = 0; r < RW; r++) {
#pragma unroll
                for (int q = 0; q < 4; q++) h[r][q] = hdot(xs[r], ys[r], zs[r], ps[q]);
                float rmax = fmaxf(fmaxf(h[r][0], h[r][1]), fmaxf(h[r][2], h[r][3]));
                g = fmaxf(g, rmax - hth[r]);
            }
            if (g >= 0.0f) {   // rare: near-NN candidates only
#pragma unroll
                for (int r = 0; r < RW; r++) {
#pragma unroll
                    for (int q = 0; q < 4; q++) {
                        if (h[r][q] >= hth[r]) {
                            float d2 = fmaf(-2.0f, h[r][q], s1[r]);
                            float w = __expf(FACT / fmaxf(d2, EPS) - m[r]);
                            sw[r] += w;
                            ax[r] = fmaf(w, ps[q].x, ax[r]);
                            ay[r] = fmaf(w, ps[q].y, ay[r]);
                            az[r] = fmaf(w, ps[q].z, az[r]);
                        }
                    }
                }
            }
        }

        // Butterfly reductions (all lanes end with totals)
#pragma unroll
        for (int r = 0; r < RW; r++) {
#pragma unroll
            for (int ofs = 16; ofs > 0; ofs >>= 1) {
                sw[r] += __shfl_xor_sync(0xFFFFFFFFu, sw[r], ofs);
                ax[r] += __shfl_xor_sync(0xFFFFFFFFu, ax[r], ofs);
                ay[r] += __shfl_xor_sync(0xFFFFFFFFu, ay[r], ofs);
                az[r] += __shfl_xor_sync(0xFFFFFFFFu, az[r], ofs);
            }
        }

        if (lane < RW) {
            int r = lane;
            int i = row0 + r;
            float inv = 1.0f / sw[r];
            float px = ax[r] * inv, py = ay[r] * inv, pz = az[r] * inv;
            out[i] = px;
            out[N + i] = py;
            out[2 * N + i] = pz;
            float dx = xs[r] - px + PD_EPS;
            float dy = ys[r] - py + PD_EPS;
            float dz = zs[r] - pz + PD_EPS;
            g_pd[i] = sqrtf(fmaf(dx, dx, fmaf(dy, dy, dz * dz)));
        }

        // Completion handshake; last unit's warp computes the mean in-kernel.
        int done;
        if (lane == 0) {
            __threadfence();                 // publish g_pd before counting (release)
            done = atomicAdd(&g_done, 1);
        }
        done = __shfl_sync(0xFFFFFFFFu, done, 0);
        if (done == UNITS - 1) {
            __threadfence();                 // acquire side: order g_pd reads after counter
            float acc = 0.f;
            for (int i = lane; i < N; i += 32) acc += __ldcg(&g_pd[i]);  // read via L2
#pragma unroll
            for (int ofs = 16; ofs > 0; ofs >>= 1)
                acc += __shfl_xor_sync(0xFFFFFFFFu, acc, ofs);
            if (lane == 0 && out_size > 3 * N) out[3 * N] = acc * (1.0f / N);
        }
    }
}

extern "C" void kernel_launch(void* const* d_in, const int* in_sizes, int n_in,
                              void* d_out, int out_size) {
    const float* pc1 = (const float*)d_in[0];
    const float* pc2 = (const float*)d_in[1];
    float* out = (float*)d_out;

    prep_kernel<<<(N + 255) / 256, 256>>>(pc2);
    soft_knn_kernel<<<CTAS, TPB>>>(pc1, out, out_size);
}

// round 8
// speedup vs baseline: 1.7062x; 1.7062x over previous
#include <cuda_runtime.h>
#include <cuda_bf16.h>
#include <math.h>

#define N 8192
#define EPS 1e-5f
#define FACT 2.0f
#define PD_EPS 1e-6f
#define CUTOFF 25.0f

#define RW 4                 // rows per unit (one CTA per unit, 2 warps split j)
#define TPB 64               // 2 warps
#define UNITS (N / RW)       // 2048 CTAs -> single wave at 14 CTAs/SM

__device__ float4 g_p2[N];   // packed {x, y, z, -0.5*(x^2+y^2+z^2)}
__device__ float g_pd[N];    // per-row pairwise distance
__device__ int g_done;       // completed-CTA counter

// h = dot(p1, p2_j) - 0.5*|p2_j|^2   (argmax h == argmin d2; d2 = s1 - 2h)
__device__ __forceinline__ float hdot(float x, float y, float z, float4 p) {
    return fmaf(x, p.x, fmaf(y, p.y, fmaf(z, p.z, p.w)));
}

__global__ void prep_kernel(const float* __restrict__ pc2) {
    int j = blockIdx.x * blockDim.x + threadIdx.x;
    if (j == 0) g_done = 0;          // re-seed every launch (graph-replay safe)
    if (j < N) {
        float x = pc2[j], y = pc2[N + j], z = pc2[2 * N + j];
        g_p2[j] = make_float4(x, y, z, -0.5f * fmaf(x, x, fmaf(y, y, z * z)));
    }
}

__global__ __launch_bounds__(TPB, 14)
void soft_knn_kernel(const float* __restrict__ pc1, float* __restrict__ out,
                     int out_size) {
    __shared__ float s_hm[2][RW];
    __shared__ float s_acc[2][RW][4];
    __shared__ int s_last;

    const int tid = threadIdx.x;
    const int lane = tid & 31;
    const int wrp = tid >> 5;
    const int row0 = blockIdx.x * RW;
    const float4* __restrict__ p2 = g_p2;

    // Query rows (redundant per thread; L1 broadcast)
    float xs[RW], ys[RW], zs[RW], s1[RW];
#pragma unroll
    for (int r = 0; r < RW; r++) {
        int i = row0 + r;
        xs[r] = pc1[i];
        ys[r] = pc1[N + i];
        zs[r] = pc1[2 * N + i];
        s1[r] = fmaf(xs[r], xs[r], fmaf(ys[r], ys[r], zs[r] * zs[r]));
    }

    // ---- Pass 1: per-row hmax; 64 threads sweep j, unroll x2 ----
    float hm[RW];
#pragma unroll
    for (int r = 0; r < RW; r++) hm[r] = -3.4e38f;

    for (int j = tid; j < N; j += 2 * TPB) {
        float4 pa = p2[j];
        float4 pb = p2[j + TPB];
#pragma unroll
        for (int r = 0; r < RW; r++)
            hm[r] = fmaxf(hm[r], fmaxf(hdot(xs[r], ys[r], zs[r], pa),
                                       hdot(xs[r], ys[r], zs[r], pb)));
    }
#pragma unroll
    for (int r = 0; r < RW; r++) {
#pragma unroll
        for (int ofs = 16; ofs > 0; ofs >>= 1)
            hm[r] = fmaxf(hm[r], __shfl_xor_sync(0xFFFFFFFFu, hm[r], ofs));
    }
    if (lane == 0) {
#pragma unroll
        for (int r = 0; r < RW; r++) s_hm[wrp][r] = hm[r];
    }
    __syncthreads();
#pragma unroll
    for (int r = 0; r < RW; r++) hm[r] = fmaxf(s_hm[0][r], s_hm[1][r]);

    // Thresholds; clamp to hmax so the argmax point ALWAYS qualifies
    // (identical fmaf chain in pass 2 reproduces h == hmax bitwise).
    float m[RW], hth[RW];
#pragma unroll
    for (int r = 0; r < RW; r++) {
        float mind2 = fmaf(-2.0f, hm[r], s1[r]);
        float mm = FACT / fmaxf(mind2, EPS);
        m[r] = mm;
        float t = (mm > CUTOFF) ? 0.5f * (s1[r] - FACT / (mm - CUTOFF)) : -3.4e38f;
        hth[r] = fminf(t, hm[r]);
    }

    // ---- Pass 2: one gate per (2 j x 4 rows) block ----
    float sw[RW], ax[RW], ay[RW], az[RW];
#pragma unroll
    for (int r = 0; r < RW; r++) { sw[r] = 0.f; ax[r] = 0.f; ay[r] = 0.f; az[r] = 0.f; }

    for (int j = tid; j < N; j += 2 * TPB) {
        float4 pa = p2[j];
        float4 pb = p2[j + TPB];
        float ha[RW], hb[RW];
        float g = -3.4e38f;
#pragma unroll
        for (int r = 0; r < RW; r++) {
            ha[r] = hdot(xs[r], ys[r], zs[r], pa);
            hb[r] = hdot(xs[r], ys[r], zs[r], pb);
            g = fmaxf(g, fmaxf(ha[r], hb[r]) - hth[r]);
        }
        if (g >= 0.0f) {   // rare: near-NN candidates only
#pragma unroll
            for (int r = 0; r < RW; r++) {
                if (ha[r] >= hth[r]) {
                    float d2 = fmaf(-2.0f, ha[r], s1[r]);
                    float w = __expf(FACT / fmaxf(d2, EPS) - m[r]);
                    sw[r] += w;
                    ax[r] = fmaf(w, pa.x, ax[r]);
                    ay[r] = fmaf(w, pa.y, ay[r]);
                    az[r] = fmaf(w, pa.z, az[r]);
                }
                if (hb[r] >= hth[r]) {
                    float d2 = fmaf(-2.0f, hb[r], s1[r]);
                    float w = __expf(FACT / fmaxf(d2, EPS) - m[r]);
                    sw[r] += w;
                    ax[r] = fmaf(w, pb.x, ax[r]);
                    ay[r] = fmaf(w, pb.y, ay[r]);
                    az[r] = fmaf(w, pb.z, az[r]);
                }
            }
        }
    }

    // Per-warp butterfly, then cross-warp combine via smem
#pragma unroll
    for (int r = 0; r < RW; r++) {
#pragma unroll
        for (int ofs = 16; ofs > 0; ofs >>= 1) {
            sw[r] += __shfl_xor_sync(0xFFFFFFFFu, sw[r], ofs);
            ax[r] += __shfl_xor_sync(0xFFFFFFFFu, ax[r], ofs);
            ay[r] += __shfl_xor_sync(0xFFFFFFFFu, ay[r], ofs);
            az[r] += __shfl_xor_sync(0xFFFFFFFFu, az[r], ofs);
        }
    }
    if (lane == 0) {
#pragma unroll
        for (int r = 0; r < RW; r++) {
            s_acc[wrp][r][0] = sw[r];
            s_acc[wrp][r][1] = ax[r];
            s_acc[wrp][r][2] = ay[r];
            s_acc[wrp][r][3] = az[r];
        }
    }
    __syncthreads();

    if (tid < RW) {
        int r = tid;
        int i = row0 + r;
        float swt = s_acc[0][r][0] + s_acc[1][r][0];
        float axt = s_acc[0][r][1] + s_acc[1][r][1];
        float ayt = s_acc[0][r][2] + s_acc[1][r][2];
        float azt = s_acc[0][r][3] + s_acc[1][r][3];
        float inv = 1.0f / swt;
        float px = axt * inv, py = ayt * inv, pz = azt * inv;
        out[i] = px;
        out[N + i] = py;
        out[2 * N + i] = pz;
        float dx = xs[r] - px + PD_EPS;
        float dy = ys[r] - py + PD_EPS;
        float dz = zs[r] - pz + PD_EPS;
        g_pd[i] = sqrtf(fmaf(dx, dx, fmaf(dy, dy, dz * dz)));
    }

    // Last-CTA mean (canonical syncthreads + threadfence + atomic pattern)
    __syncthreads();
    __threadfence();
    if (tid == 0) s_last = (atomicAdd(&g_done, 1) == UNITS - 1);
    __syncthreads();
    if (s_last) {
        float acc = 0.f;
        for (int i = tid; i < N; i += TPB) acc += __ldcg(&g_pd[i]);
#pragma unroll
        for (int ofs = 16; ofs > 0; ofs >>= 1)
            acc += __shfl_xor_sync(0xFFFFFFFFu, acc, ofs);
        if (lane == 0) s_acc[0][0][wrp] = acc;
        __syncthreads();
        if (tid == 0 && out_size > 3 * N)
            out[3 * N] = (s_acc[0][0][0] + s_acc[0][0][1]) * (1.0f / N);
    }
}

extern "C" void kernel_launch(void* const* d_in, const int* in_sizes, int n_in,
                              void* d_out, int out_size) {
    const float* pc1 = (const float*)d_in[0];
    const float* pc2 = (const float*)d_in[1];
    float* out = (float*)d_out;

    prep_kernel<<<(N + 255) / 256, 256>>>(pc2);
    soft_knn_kernel<<<UNITS, TPB>>>(pc1, out, out_size);
}

// round 9
// speedup vs baseline: 2.0326x; 1.1914x over previous
#include <cuda_runtime.h>
#include <cuda_bf16.h>
#include <math.h>

#define N 8192
#define EPS 1e-5f
#define FACT 2.0f
#define PD_EPS 1e-6f
#define CUTOFF 25.0f
#define DENSE_TH 50.0f   // rows with m < 50 go to the dense kernel

#define RW 4
#define TPB 64
#define GRID (N / RW)    // 2048 CTAs; 16 CTAs/SM -> single wave, 32 warps/SM

__device__ float4 g_p2[N];    // packed {x, y, z, -0.5*|p|^2}
__device__ float g_rowm[N];   // softmax max arg per row (exact)
__device__ float g_rowth[N];  // gate threshold in h-space (+inf for dense rows)
__device__ float g_pd[N];     // per-row pairwise distance

// h = dot(p1, p2_j) - 0.5*|p2_j|^2  (argmax h == argmin d2; d2 = s1 - 2h)
__device__ __forceinline__ float hdot(float x, float y, float z, float4 p) {
    return fmaf(x, p.x, fmaf(y, p.y, fmaf(z, p.z, p.w)));
}

__global__ void prep_kernel(const float* __restrict__ pc2) {
    int j = blockIdx.x * blockDim.x + threadIdx.x;
    if (j < N) {
        float x = pc2[j], y = pc2[N + j], z = pc2[2 * N + j];
        g_p2[j] = make_float4(x, y, z, -0.5f * fmaf(x, x, fmaf(y, y, z * z)));
    }
}

// ---- K1: exact per-row hmax -> m, hth (uniform cost) ----
__global__ __launch_bounds__(TPB, 16)
void max_kernel(const float* __restrict__ pc1) {
    __shared__ float s_hm[2][RW];
    const int tid = threadIdx.x;
    const int lane = tid & 31;
    const int wrp = tid >> 5;
    const int row0 = blockIdx.x * RW;
    const float4* __restrict__ p2 = g_p2;

    float xs[RW], ys[RW], zs[RW], s1[RW];
#pragma unroll
    for (int r = 0; r < RW; r++) {
        int i = row0 + r;
        xs[r] = pc1[i];
        ys[r] = pc1[N + i];
        zs[r] = pc1[2 * N + i];
        s1[r] = fmaf(xs[r], xs[r], fmaf(ys[r], ys[r], zs[r] * zs[r]));
    }

    float hm[RW];
#pragma unroll
    for (int r = 0; r < RW; r++) hm[r] = -3.4e38f;

    for (int j = tid; j < N; j += 4 * TPB) {   // unroll x4, MLP 4
        float4 pa = p2[j];
        float4 pb = p2[j + TPB];
        float4 pc = p2[j + 2 * TPB];
        float4 pd = p2[j + 3 * TPB];
#pragma unroll
        for (int r = 0; r < RW; r++) {
            float a = fmaxf(hdot(xs[r], ys[r], zs[r], pa),
                            hdot(xs[r], ys[r], zs[r], pb));
            float b = fmaxf(hdot(xs[r], ys[r], zs[r], pc),
                            hdot(xs[r], ys[r], zs[r], pd));
            hm[r] = fmaxf(hm[r], fmaxf(a, b));
        }
    }
#pragma unroll
    for (int r = 0; r < RW; r++) {
#pragma unroll
        for (int ofs = 16; ofs > 0; ofs >>= 1)
            hm[r] = fmaxf(hm[r], __shfl_xor_sync(0xFFFFFFFFu, hm[r], ofs));
    }
    if (lane == 0) {
#pragma unroll
        for (int r = 0; r < RW; r++) s_hm[wrp][r] = hm[r];
    }
    __syncthreads();

    if (tid < RW) {
        int r = tid;
        float h = fmaxf(s_hm[0][r], s_hm[1][r]);           // exact fp32 row max
        float mind2 = fmaf(-2.0f, h, s1[r]);
        float mm = FACT / fmaxf(mind2, EPS);
        float hth;
        if (mm < DENSE_TH) {
            hth = __int_as_float(0x7f800000);               // +inf: gate off in K2
        } else {
            float t = 0.5f * (s1[r] - FACT / (mm - CUTOFF));
            hth = fminf(t, h);   // clamp: argmax always qualifies bitwise in K2
        }
        g_rowm[row0 + r] = mm;
        g_rowth[row0 + r] = hth;
    }
}

// ---- K2: gated softmax accumulation for sparse rows (uniform cost) ----
__global__ __launch_bounds__(TPB, 16)
void acc_kernel(const float* __restrict__ pc1, float* __restrict__ out) {
    __shared__ float s_acc[2][RW][4];
    const int tid = threadIdx.x;
    const int lane = tid & 31;
    const int wrp = tid >> 5;
    const int row0 = blockIdx.x * RW;
    const float4* __restrict__ p2 = g_p2;

    float xs[RW], ys[RW], zs[RW], s1[RW], m[RW], hth[RW];
#pragma unroll
    for (int r = 0; r < RW; r++) {
        int i = row0 + r;
        xs[r] = pc1[i];
        ys[r] = pc1[N + i];
        zs[r] = pc1[2 * N + i];
        s1[r] = fmaf(xs[r], xs[r], fmaf(ys[r], ys[r], zs[r] * zs[r]));
        m[r] = g_rowm[i];
        hth[r] = g_rowth[i];
    }

    float sw[RW], ax[RW], ay[RW], az[RW];
#pragma unroll
    for (int r = 0; r < RW; r++) { sw[r] = 0.f; ax[r] = 0.f; ay[r] = 0.f; az[r] = 0.f; }

    for (int j = tid; j < N; j += 2 * TPB) {   // unroll x2
        float4 pa = p2[j];
        float4 pb = p2[j + TPB];
        float ha[RW], hb[RW];
        float g = -3.4e38f;
#pragma unroll
        for (int r = 0; r < RW; r++) {
            ha[r] = hdot(xs[r], ys[r], zs[r], pa);   // identical chain to K1
            hb[r] = hdot(xs[r], ys[r], zs[r], pb);
            g = fmaxf(g, fmaxf(ha[r], hb[r]) - hth[r]);
        }
        if (g >= 0.0f) {   // rare: tight qualifier ball for every sparse row
#pragma unroll
            for (int r = 0; r < RW; r++) {
                if (ha[r] >= hth[r]) {
                    float d2 = fmaf(-2.0f, ha[r], s1[r]);
                    float w = __expf(FACT / fmaxf(d2, EPS) - m[r]);
                    sw[r] += w;
                    ax[r] = fmaf(w, pa.x, ax[r]);
                    ay[r] = fmaf(w, pa.y, ay[r]);
                    az[r] = fmaf(w, pa.z, az[r]);
                }
                if (hb[r] >= hth[r]) {
                    float d2 = fmaf(-2.0f, hb[r], s1[r]);
                    float w = __expf(FACT / fmaxf(d2, EPS) - m[r]);
                    sw[r] += w;
                    ax[r] = fmaf(w, pb.x, ax[r]);
                    ay[r] = fmaf(w, pb.y, ay[r]);
                    az[r] = fmaf(w, pb.z, az[r]);
                }
            }
        }
    }

#pragma unroll
    for (int r = 0; r < RW; r++) {
#pragma unroll
        for (int ofs = 16; ofs > 0; ofs >>= 1) {
            sw[r] += __shfl_xor_sync(0xFFFFFFFFu, sw[r], ofs);
            ax[r] += __shfl_xor_sync(0xFFFFFFFFu, ax[r], ofs);
            ay[r] += __shfl_xor_sync(0xFFFFFFFFu, ay[r], ofs);
            az[r] += __shfl_xor_sync(0xFFFFFFFFu, az[r], ofs);
        }
    }
    if (lane == 0) {
#pragma unroll
        for (int r = 0; r < RW; r++) {
            s_acc[wrp][r][0] = sw[r];
            s_acc[wrp][r][1] = ax[r];
            s_acc[wrp][r][2] = ay[r];
            s_acc[wrp][r][3] = az[r];
        }
    }
    __syncthreads();

    if (tid < RW) {
        int r = tid;
        if (m[r] >= DENSE_TH) {             // dense rows owned by dense_kernel
            int i = row0 + r;
            float swt = s_acc[0][r][0] + s_acc[1][r][0];
            float axt = s_acc[0][r][1] + s_acc[1][r][1];
            float ayt = s_acc[0][r][2] + s_acc[1][r][2];
            float azt = s_acc[0][r][3] + s_acc[1][r][3];
            float inv = 1.0f / swt;
            float px = axt * inv, py = ayt * inv, pz = azt * inv;
            out[i] = px;
            out[N + i] = py;
            out[2 * N + i] = pz;
            float dx = xs[r] - px + PD_EPS;
            float dy = ys[r] - py + PD_EPS;
            float dz = zs[r] - pz + PD_EPS;
            g_pd[i] = sqrtf(fmaf(dx, dx, fmaf(dy, dy, dz * dz)));
        }
    }
}

// ---- K3: dense rows, one CTA per row; non-dense CTAs exit immediately ----
__global__ __launch_bounds__(256)
void dense_kernel(const float* __restrict__ pc1, float* __restrict__ out) {
    __shared__ float s_red[8][4];
    const int row = blockIdx.x;
    const float m = g_rowm[row];
    if (m >= DENSE_TH) return;            // sparse: handled by acc_kernel

    const int tid = threadIdx.x;
    const int lane = tid & 31;
    const int wrp = tid >> 5;
    const float4* __restrict__ p2 = g_p2;

    float x1 = pc1[row], y1 = pc1[N + row], z1 = pc1[2 * N + row];
    float s1 = fmaf(x1, x1, fmaf(y1, y1, z1 * z1));

    float sw = 0.f, ax = 0.f, ay = 0.f, az = 0.f;
    for (int j = tid; j < N; j += 256) {
        float4 p = p2[j];
        float h = hdot(x1, y1, z1, p);
        float d2 = fmaf(-2.0f, h, s1);
        float w = __expf(FACT / fmaxf(d2, EPS) - m);   // m exact -> no overflow
        sw += w;
        ax = fmaf(w, p.x, ax);
        ay = fmaf(w, p.y, ay);
        az = fmaf(w, p.z, az);
    }
#pragma unroll
    for (int ofs = 16; ofs > 0; ofs >>= 1) {
        sw += __shfl_xor_sync(0xFFFFFFFFu, sw, ofs);
        ax += __shfl_xor_sync(0xFFFFFFFFu, ax, ofs);
        ay += __shfl_xor_sync(0xFFFFFFFFu, ay, ofs);
        az += __shfl_xor_sync(0xFFFFFFFFu, az, ofs);
    }
    if (lane == 0) {
        s_red[wrp][0] = sw;
        s_red[wrp][1] = ax;
        s_red[wrp][2] = ay;
        s_red[wrp][3] = az;
    }
    __syncthreads();
    if (tid == 0) {
        float swt = 0.f, axt = 0.f, ayt = 0.f, azt = 0.f;
#pragma unroll
        for (int w8 = 0; w8 < 8; w8++) {   // fixed order: deterministic
            swt += s_red[w8][0];
            axt += s_red[w8][1];
            ayt += s_red[w8][2];
            azt += s_red[w8][3];
        }
        float inv = 1.0f / swt;
        float px = axt * inv, py = ayt * inv, pz = azt * inv;
        out[row] = px;
        out[N + row] = py;
        out[2 * N + row] = pz;
        float dx = x1 - px + PD_EPS;
        float dy = y1 - py + PD_EPS;
        float dz = z1 - pz + PD_EPS;
        g_pd[row] = sqrtf(fmaf(dx, dx, fmaf(dy, dy, dz * dz)));
    }
}

// ---- deterministic fixed-order mean ----
__global__ void mean_kernel(float* __restrict__ out, int out_size) {
    __shared__ float ss[32];
    const int tid = threadIdx.x;
    float acc = 0.f;
    for (int i = tid; i < N; i += 1024) acc += g_pd[i];
#pragma unroll
    for (int ofs = 16; ofs > 0; ofs >>= 1)
        acc += __shfl_xor_sync(0xFFFFFFFFu, acc, ofs);
    if ((tid & 31) == 0) ss[tid >> 5] = acc;
    __syncthreads();
    if (tid < 32) {
        float a = ss[tid];
#pragma unroll
        for (int ofs = 16; ofs > 0; ofs >>= 1)
            a += __shfl_xor_sync(0xFFFFFFFFu, a, ofs);
        if (tid == 0 && out_size > 3 * N) out[3 * N] = a * (1.0f / N);
    }
}

extern "C" void kernel_launch(void* const* d_in, const int* in_sizes, int n_in,
                              void* d_out, int out_size) {
    const float* pc1 = (const float*)d_in[0];
    const float* pc2 = (const float*)d_in[1];
    float* out = (float*)d_out;

    prep_kernel<<<(N + 255) / 256, 256>>>(pc2);
    max_kernel<<<GRID, TPB>>>(pc1);
    acc_kernel<<<GRID, TPB>>>(pc1, out);
    dense_kernel<<<N, 256>>>(pc1, out);
    mean_kernel<<<1, 1024>>>(out, out_size);
}

// round 10
// speedup vs baseline: 2.2521x; 1.1080x over previous
#include <cuda_runtime.h>
#include <cuda_bf16.h>
#include <math.h>

#define N 8192
#define EPS 1e-5f
#define FACT 2.0f
#define PD_EPS 1e-6f
#define CUTOFF 25.0f
#define DENSE_TH 50.0f   // rows with m < 50 handled by dense_kernel

#define RW 4
#define TPB 64
#define GRID (N / RW)    // 2048 CTAs
#define GRID_D 592       // dense kernel CTAs (4/SM)
#define TPB_D 128

__device__ float4 g_p2[N];        // packed {x, y, z, -0.5*|p|^2}
__device__ float g_rowm[N];       // softmax max arg per row (exact)
__device__ float g_pd[N];         // per-row pairwise distance
__device__ int g_dense_rows[N];   // compacted dense row indices
__device__ int g_dense_cnt;      // number of dense rows
__device__ int g_done;           // dense-kernel completion counter

// h = dot(p1, p2_j) - 0.5*|p2_j|^2  (argmax h == argmin d2; d2 = s1 - 2h)
__device__ __forceinline__ float hdot(float x, float y, float z, float4 p) {
    return fmaf(x, p.x, fmaf(y, p.y, fmaf(z, p.z, p.w)));
}

__global__ void prep_kernel(const float* __restrict__ pc2) {
    int j = blockIdx.x * blockDim.x + threadIdx.x;
    if (j == 0) { g_dense_cnt = 0; g_done = 0; }   // re-seed (graph-replay safe)
    if (j < N) {
        float x = pc2[j], y = pc2[N + j], z = pc2[2 * N + j];
        g_p2[j] = make_float4(x, y, z, -0.5f * fmaf(x, x, fmaf(y, y, z * z)));
    }
}

// ---- Fused: pass1 max -> classify -> pass2 gated acc (sparse rows only) ----
__global__ __launch_bounds__(TPB, 14)
void soft_knn_kernel(const float* __restrict__ pc1, float* __restrict__ out) {
    __shared__ float s_hm[2][RW];
    __shared__ float s_acc[2][RW][4];

    const int tid = threadIdx.x;
    const int lane = tid & 31;
    const int wrp = tid >> 5;
    const int row0 = blockIdx.x * RW;
    const float4* __restrict__ p2 = g_p2;

    float xs[RW], ys[RW], zs[RW], s1[RW];
#pragma unroll
    for (int r = 0; r < RW; r++) {
        int i = row0 + r;
        xs[r] = pc1[i];
        ys[r] = pc1[N + i];
        zs[r] = pc1[2 * N + i];
        s1[r] = fmaf(xs[r], xs[r], fmaf(ys[r], ys[r], zs[r] * zs[r]));
    }

    // ---- Pass 1: per-row hmax; 64 threads sweep j, unroll x4 ----
    float hm[RW];
#pragma unroll
    for (int r = 0; r < RW; r++) hm[r] = -3.4e38f;

    for (int j = tid; j < N; j += 4 * TPB) {
        float4 pa = p2[j];
        float4 pb = p2[j + TPB];
        float4 pc = p2[j + 2 * TPB];
        float4 pd = p2[j + 3 * TPB];
#pragma unroll
        for (int r = 0; r < RW; r++) {
            float a = fmaxf(hdot(xs[r], ys[r], zs[r], pa),
                            hdot(xs[r], ys[r], zs[r], pb));
            float b = fmaxf(hdot(xs[r], ys[r], zs[r], pc),
                            hdot(xs[r], ys[r], zs[r], pd));
            hm[r] = fmaxf(hm[r], fmaxf(a, b));
        }
    }
#pragma unroll
    for (int r = 0; r < RW; r++) {
#pragma unroll
        for (int ofs = 16; ofs > 0; ofs >>= 1)
            hm[r] = fmaxf(hm[r], __shfl_xor_sync(0xFFFFFFFFu, hm[r], ofs));
    }
    if (lane == 0) {
#pragma unroll
        for (int r = 0; r < RW; r++) s_hm[wrp][r] = hm[r];
    }
    __syncthreads();

    // Thresholds (computed redundantly per thread; identical results).
    // Dense rows: gate off (+inf) here, handled by dense_kernel.
    float m[RW], hth[RW];
#pragma unroll
    for (int r = 0; r < RW; r++) {
        float h = fmaxf(s_hm[0][r], s_hm[1][r]);   // exact fp32 row max
        float mind2 = fmaf(-2.0f, h, s1[r]);
        float mm = FACT / fmaxf(mind2, EPS);
        m[r] = mm;
        if (mm < DENSE_TH) {
            hth[r] = __int_as_float(0x7f800000);    // +inf
        } else {
            float t = 0.5f * (s1[r] - FACT / (mm - CUTOFF));
            hth[r] = fminf(t, h);  // clamp: argmax qualifies bitwise in pass 2
        }
    }
    // Append dense rows to compact list (one thread per row)
    if (tid < RW) {
        int r = tid;
        g_rowm[row0 + r] = m[r];
        if (m[r] < DENSE_TH) {
            int e = atomicAdd(&g_dense_cnt, 1);
            g_dense_rows[e] = row0 + r;
        }
    }

    // ---- Pass 2: gated accumulation (identical hdot chain) ----
    float sw[RW], ax[RW], ay[RW], az[RW];
#pragma unroll
    for (int r = 0; r < RW; r++) { sw[r] = 0.f; ax[r] = 0.f; ay[r] = 0.f; az[r] = 0.f; }

    for (int j = tid; j < N; j += 2 * TPB) {
        float4 pa = p2[j];
        float4 pb = p2[j + TPB];
        float ha[RW], hb[RW];
        float g = -3.4e38f;
#pragma unroll
        for (int r = 0; r < RW; r++) {
            ha[r] = hdot(xs[r], ys[r], zs[r], pa);
            hb[r] = hdot(xs[r], ys[r], zs[r], pb);
            g = fmaxf(g, fmaxf(ha[r], hb[r]) - hth[r]);
        }
        if (g >= 0.0f) {   // rare: tight qualifier ball for sparse rows
#pragma unroll
            for (int r = 0; r < RW; r++) {
                if (ha[r] >= hth[r]) {
                    float d2 = fmaf(-2.0f, ha[r], s1[r]);
                    float w = __expf(FACT / fmaxf(d2, EPS) - m[r]);
                    sw[r] += w;
                    ax[r] = fmaf(w, pa.x, ax[r]);
                    ay[r] = fmaf(w, pa.y, ay[r]);
                    az[r] = fmaf(w, pa.z, az[r]);
                }
                if (hb[r] >= hth[r]) {
                    float d2 = fmaf(-2.0f, hb[r], s1[r]);
                    float w = __expf(FACT / fmaxf(d2, EPS) - m[r]);
                    sw[r] += w;
                    ax[r] = fmaf(w, pb.x, ax[r]);
                    ay[r] = fmaf(w, pb.y, ay[r]);
                    az[r] = fmaf(w, pb.z, az[r]);
                }
            }
        }
    }

#pragma unroll
    for (int r = 0; r < RW; r++) {
#pragma unroll
        for (int ofs = 16; ofs > 0; ofs >>= 1) {
            sw[r] += __shfl_xor_sync(0xFFFFFFFFu, sw[r], ofs);
            ax[r] += __shfl_xor_sync(0xFFFFFFFFu, ax[r], ofs);
            ay[r] += __shfl_xor_sync(0xFFFFFFFFu, ay[r], ofs);
            az[r] += __shfl_xor_sync(0xFFFFFFFFu, az[r], ofs);
        }
    }
    if (lane == 0) {
#pragma unroll
        for (int r = 0; r < RW; r++) {
            s_acc[wrp][r][0] = sw[r];
            s_acc[wrp][r][1] = ax[r];
            s_acc[wrp][r][2] = ay[r];
            s_acc[wrp][r][3] = az[r];
        }
    }
    __syncthreads();

    if (tid < RW) {
        int r = tid;
        if (m[r] >= DENSE_TH) {             // sparse rows finalized here
            int i = row0 + r;
            float swt = s_acc[0][r][0] + s_acc[1][r][0];
            float axt = s_acc[0][r][1] + s_acc[1][r][1];
            float ayt = s_acc[0][r][2] + s_acc[1][r][2];
            float azt = s_acc[0][r][3] + s_acc[1][r][3];
            float inv = 1.0f / swt;
            float px = axt * inv, py = ayt * inv, pz = azt * inv;
            out[i] = px;
            out[N + i] = py;
            out[2 * N + i] = pz;
            float dx = xs[r] - px + PD_EPS;
            float dy = ys[r] - py + PD_EPS;
            float dz = zs[r] - pz + PD_EPS;
            g_pd[i] = sqrtf(fmaf(dx, dx, fmaf(dy, dy, dz * dz)));
        }
    }
}

// ---- Dense rows via compact list; last CTA computes the mean ----
__global__ __launch_bounds__(TPB_D)
void dense_kernel(const float* __restrict__ pc1, float* __restrict__ out,
                  int out_size) {
    __shared__ float s_red[4][4];
    __shared__ float s_mean[4];
    __shared__ int s_last;

    const int tid = threadIdx.x;
    const int lane = tid & 31;
    const int wrp = tid >> 5;
    const int cnt = g_dense_cnt;             // written by previous kernel
    const float4* __restrict__ p2 = g_p2;

    for (int e = blockIdx.x; e < cnt; e += GRID_D) {
        const int row = g_dense_rows[e];
        const float m = g_rowm[row];
        float x1 = pc1[row], y1 = pc1[N + row], z1 = pc1[2 * N + row];
        float s1 = fmaf(x1, x1, fmaf(y1, y1, z1 * z1));

        float sw = 0.f, ax = 0.f, ay = 0.f, az = 0.f;
        for (int j = tid; j < N; j += 4 * TPB_D) {   // unroll x4, MLP 4
            float4 ps[4] = {p2[j], p2[j + TPB_D], p2[j + 2 * TPB_D], p2[j + 3 * TPB_D]};
#pragma unroll
            for (int q = 0; q < 4; q++) {
                float h = hdot(x1, y1, z1, ps[q]);
                float d2 = fmaf(-2.0f, h, s1);
                float w = __expf(FACT / fmaxf(d2, EPS) - m);   // m exact: no overflow
                sw += w;
                ax = fmaf(w, ps[q].x, ax);
                ay = fmaf(w, ps[q].y, ay);
                az = fmaf(w, ps[q].z, az);
            }
        }
#pragma unroll
        for (int ofs = 16; ofs > 0; ofs >>= 1) {
            sw += __shfl_xor_sync(0xFFFFFFFFu, sw, ofs);
            ax += __shfl_xor_sync(0xFFFFFFFFu, ax, ofs);
            ay += __shfl_xor_sync(0xFFFFFFFFu, ay, ofs);
            az += __shfl_xor_sync(0xFFFFFFFFu, az, ofs);
        }
        if (lane == 0) {
            s_red[wrp][0] = sw;
            s_red[wrp][1] = ax;
            s_red[wrp][2] = ay;
            s_red[wrp][3] = az;
        }
        __syncthreads();
        if (tid == 0) {
            float swt = 0.f, axt = 0.f, ayt = 0.f, azt = 0.f;
#pragma unroll
            for (int w4 = 0; w4 < 4; w4++) {   // fixed order: deterministic
                swt += s_red[w4][0];
                axt += s_red[w4][1];
                ayt += s_red[w4][2];
                azt += s_red[w4][3];
            }
            float inv = 1.0f / swt;
            float px = axt * inv, py = ayt * inv, pz = azt * inv;
            out[row] = px;
            out[N + row] = py;
            out[2 * N + row] = pz;
            float dx = x1 - px + PD_EPS;
            float dy = y1 - py + PD_EPS;
            float dz = z1 - pz + PD_EPS;
            g_pd[row] = sqrtf(fmaf(dx, dx, fmaf(dy, dy, dz * dz)));
        }
        __syncthreads();
    }

    // Completion handshake (ALL CTAs, incl. ones with no list entries)
    __threadfence();
    if (tid == 0) s_last = (atomicAdd(&g_done, 1) == GRID_D - 1);
    __syncthreads();
    if (s_last) {
        __threadfence();   // acquire: order g_pd reads after the counter
        float acc = 0.f;
        for (int i = tid; i < N; i += TPB_D) acc += __ldcg(&g_pd[i]);
#pragma unroll
        for (int ofs = 16; ofs > 0; ofs >>= 1)
            acc += __shfl_xor_sync(0xFFFFFFFFu, acc, ofs);
        if (lane == 0) s_mean[wrp] = acc;
        __syncthreads();
        if (tid == 0 && out_size > 3 * N)
            out[3 * N] = (s_mean[0] + s_mean[1] + s_mean[2] + s_mean[3]) * (1.0f / N);
    }
}

extern "C" void kernel_launch(void* const* d_in, const int* in_sizes, int n_in,
                              void* d_out, int out_size) {
    const float* pc1 = (const float*)d_in[0];
    const float* pc2 = (const float*)d_in[1];
    float* out = (float*)d_out;

    prep_kernel<<<(N + 255) / 256, 256>>>(pc2);
    soft_knn_kernel<<<GRID, TPB>>>(pc1, out);
    dense_kernel<<<GRID_D, TPB_D>>>(pc1, out, out_size);
}